// round 15
// baseline (speedup 1.0000x reference)
// ============================================================================
// rNet_62285615727179 rev R15
// GCN(7→32)+relu → GAT(32→64)+relu → GCN(64→128)+relu → GAT(128→2) → log_softmax
// N=100k, E=1.6M (+100k self-loops).
// Dense: RNE-bf16 operands / fp32 accumulate (jax DEFAULT matmul emulation).
// Sparse: dst-bucketed CSR, gather-only. L2 GEMM+alpha fused; L3 gather fused
// directly into the 128→2 head GEMM (no 128-ch aggregate intermediate).
// ============================================================================
#include <cuda_runtime.h>
#include <cuda_bf16.h>
#include <math.h>

namespace r15 {

constexpr int RN  = 100000;
constexpr int RE  = 1600000;
constexpr int RT  = RE + RN;
constexpr int RSB = 512;
constexpr int RSG = (RN + RSB - 1) / RSB;

__device__ int   rSrc[RT];
__device__ int   rDst[RT];
__device__ int   rDeg[RN];
__device__ float rNrm[RN];
__device__ int   rIs64;

__device__ int   rLoc[RN];
__device__ int   rTot[RSG];
__device__ int   rTotE[RSG];
__device__ int   rRow[RN + 1];
__device__ int   rCur[RN];
__device__ int   rAdj[RT];

__device__ float rH1[RN * 32];
__device__ float rG1[RN * 32];
__device__ float rH2[RN * 64];
__device__ float rG2[RN * 64];
__device__ float rH3[(size_t)RN * 128];
__device__ float rH4[RN * 2];
__device__ float rG4[RN * 2];
__device__ float rAs[RN];
__device__ float rAd[RN];

__device__ __forceinline__ float rLk(float x) { return x > 0.f ? x : 0.2f * x; }
__device__ __forceinline__ float rBf(float x) {
    return __bfloat162float(__float2bfloat16(x));   // RNE bf16 operand rounding
}

// ------------------------------- graph ------------------------------------------
__global__ void rkProbe(const void* raw) {
    const int* p = (const int*)raw;
    int m = 0;
#pragma unroll
    for (int i = 1; i < 128; i += 2) m |= p[i];
    rIs64 = (m == 0);
}

__global__ void rkDecode(const void* raw) {
    int e = blockIdx.x * blockDim.x + threadIdx.x;
    if (e >= RT) return;
    int s, d;
    if (e >= RE) {
        s = d = e - RE;
    } else if (rIs64) {
        const long long* p = (const long long*)raw;
        s = (int)p[e]; d = (int)p[RE + e];
    } else {
        const int* p = (const int*)raw;
        s = p[e]; d = p[RE + e];
    }
    rSrc[e] = s; rDst[e] = d;
    atomicAdd(&rDeg[d], 1);
}

__global__ void rkScanA() {
    __shared__ int sh[RSB];
    int t = threadIdx.x, i = blockIdx.x * RSB + t;
    int v = (i < RN) ? rDeg[i] : 0;
    sh[t] = v; __syncthreads();
    for (int o = 1; o < RSB; o <<= 1) {
        int w = (t >= o) ? sh[t - o] : 0; __syncthreads();
        sh[t] += w; __syncthreads();
    }
    if (i < RN) rLoc[i] = sh[t] - v;
    if (t == RSB - 1) rTot[blockIdx.x] = sh[t];
}

__global__ void rkScanB() {
    __shared__ int sh[256];
    int t = threadIdx.x;
    int v = (t < RSG) ? rTot[t] : 0;
    sh[t] = v; __syncthreads();
    for (int o = 1; o < 256; o <<= 1) {
        int w = (t >= o) ? sh[t - o] : 0; __syncthreads();
        sh[t] += w; __syncthreads();
    }
    if (t < RSG) rTotE[t] = sh[t] - v;
}

__global__ void rkScanC() {
    int i = blockIdx.x * blockDim.x + threadIdx.x;
    if (i < RN) {
        rRow[i] = rLoc[i] + rTotE[i / RSB];
        int dg = rDeg[i];
        rNrm[i] = dg > 0 ? rsqrtf((float)dg) : 0.f;
    }
    if (i == 0) rRow[RN] = RT;
}

__global__ void rkPlace() {
    int e = blockIdx.x * blockDim.x + threadIdx.x;
    if (e >= RT) return;
    int d = rDst[e];
    rAdj[rRow[d] + atomicAdd(&rCur[d], 1)] = rSrc[e];
}

// ------------------------------ dense layers -------------------------------------
template <int CI, int CO, int RW, bool PRELU>
__global__ void rkProj(const float* __restrict__ in, const float* __restrict__ W,
                       const float* __restrict__ bias, float* __restrict__ out) {
    __shared__ float sw[CI * CO];
    __shared__ float sx[RW][CI];
    int flat = threadIdx.y * CO + threadIdx.x;
    for (int i = flat; i < CI * CO; i += CO * RW) sw[i] = rBf(W[i]);
    int n = blockIdx.x * RW + threadIdx.y;
    if (n < RN && threadIdx.x < CI) {
        float v = in[(size_t)n * CI + threadIdx.x];
        if (PRELU) v = fmaxf(v + bias[threadIdx.x], 0.f);
        sx[threadIdx.y][threadIdx.x] = rBf(v);
    }
    __syncthreads();
    if (n >= RN) return;
    float a = 0.f;
#pragma unroll
    for (int k = 0; k < CI; k++)
        a = fmaf(sx[threadIdx.y][k], sw[k * CO + threadIdx.x], a);
    out[(size_t)n * CO + threadIdx.x] = a;
}

// 32→64 projection with relu(in+bias) input AND fused alpha scores.
__global__ void rkProj64A(const float* __restrict__ in, const float* __restrict__ W,
                          const float* __restrict__ bias,
                          const float* __restrict__ aS, const float* __restrict__ aD,
                          float* __restrict__ out) {
    constexpr int CI = 32, CO = 64, RW = 4;
    __shared__ float sw[CI * CO];
    __shared__ float sx[RW][CI];
    __shared__ float red[RW][2][2];
    int tx = threadIdx.x, ty = threadIdx.y;
    int flat = ty * CO + tx;
    for (int i = flat; i < CI * CO; i += CO * RW) sw[i] = rBf(W[i]);
    int n = blockIdx.x * RW + ty;
    if (n < RN && tx < CI) {
        float v = fmaxf(in[(size_t)n * CI + tx] + bias[tx], 0.f);
        sx[ty][tx] = rBf(v);
    }
    __syncthreads();

    float a = 0.f;
    if (n < RN) {
#pragma unroll
        for (int k = 0; k < CI; k++)
            a = fmaf(sx[ty][k], sw[k * CO + tx], a);
        out[(size_t)n * CO + tx] = a;
    }

    float pS = (n < RN) ? rBf(a) * rBf(aS[tx]) : 0.f;
    float pD = (n < RN) ? rBf(a) * rBf(aD[tx]) : 0.f;
#pragma unroll
    for (int o = 16; o; o >>= 1) {
        pS += __shfl_xor_sync(~0u, pS, o);
        pD += __shfl_xor_sync(~0u, pD, o);
    }
    if ((tx & 31) == 0) {
        red[ty][tx >> 5][0] = pS;
        red[ty][tx >> 5][1] = pD;
    }
    __syncthreads();
    if (tx == 0 && n < RN) {
        rAs[n] = red[ty][0][0] + red[ty][1][0];
        rAd[n] = red[ty][0][1] + red[ty][1][1];
    }
}

// ----------------------------- sparse aggregation ---------------------------------
__global__ void rkGcn32(const float* __restrict__ h, float* __restrict__ y) {
    int tid = blockIdx.x * blockDim.x + threadIdx.x;
    int n = tid >> 4, L = tid & 15;
    if (n >= RN) return;
    int lo = rRow[n], hi = rRow[n + 1];
    float me = rNrm[n];
    float a0 = 0.f, a1 = 0.f;
    for (int i = lo; i < hi; i++) {
        int s = __ldg(&rAdj[i]);
        float f = __ldg(&rNrm[s]) * me;
        a0 = fmaf(f, __ldg(&h[(size_t)s * 32 + L]), a0);
        a1 = fmaf(f, __ldg(&h[(size_t)s * 32 + 16 + L]), a1);
    }
    y[(size_t)n * 32 + L] = a0;
    y[(size_t)n * 32 + 16 + L] = a1;
}

__global__ void rkGat64(const float2* __restrict__ h, float2* __restrict__ y) {
    __shared__ float sWgt[8][32];
    int wid = threadIdx.x >> 5;
    int n = (blockIdx.x * blockDim.x + threadIdx.x) >> 5;
    int L = threadIdx.x & 31;
    if (n >= RN) return;
    int lo = rRow[n], hi = rRow[n + 1];
    float cd = rAd[n];

    float mx = -INFINITY;
    for (int i = lo + L; i < hi; i += 32)
        mx = fmaxf(mx, rLk(__ldg(&rAs[__ldg(&rAdj[i])]) + cd));
#pragma unroll
    for (int o = 16; o; o >>= 1) mx = fmaxf(mx, __shfl_xor_sync(~0u, mx, o));

    float dn = 0.f;
    for (int i = lo + L; i < hi; i += 32)
        dn += expf(rLk(__ldg(&rAs[__ldg(&rAdj[i])]) + cd) - mx);
#pragma unroll
    for (int o = 16; o; o >>= 1) dn += __shfl_xor_sync(~0u, dn, o);
    float iv = 1.f / (dn + 1e-16f);

    float2 a = make_float2(0.f, 0.f);
    for (int base = lo; base < hi; base += 32) {
        int i = base + L;
        sWgt[wid][L] = (i < hi)
            ? expf(rLk(__ldg(&rAs[__ldg(&rAdj[i])]) + cd) - mx) * iv : 0.f;
        __syncwarp();
        int cnt = min(32, hi - base);
        for (int j = 0; j < cnt; j++) {
            int s = __ldg(&rAdj[base + j]);
            float w = sWgt[wid][j];
            float2 v = __ldg(&h[(size_t)s * 32 + L]);
            a.x = fmaf(w, v.x, a.x);
            a.y = fmaf(w, v.y, a.y);
        }
        __syncwarp();
    }
    y[(size_t)n * 32 + L] = a;
}

// FUSED: 128-ch GCN gather (from h3) + relu(+b3) + 128→2 head GEMM + alpha.
// Warp per node; lane L owns channels 4L..4L+3 (float4).
__global__ void rkGatherHead(const float4* __restrict__ h3,
                             const float* __restrict__ W,
                             const float* __restrict__ b3,
                             const float* __restrict__ aS,
                             const float* __restrict__ aD) {
    int n = (blockIdx.x * blockDim.x + threadIdx.x) >> 5;
    int L = threadIdx.x & 31;
    if (n >= RN) return;
    int lo = rRow[n], hi = rRow[n + 1];
    float me = rNrm[n];

    // GCN gather: acc = sum_s nrm(s)*nrm(n) * h3[s, 4L..4L+3]
    float4 acc = make_float4(0.f, 0.f, 0.f, 0.f);
    if (lo < hi) {
        int sCur = __ldg(&rAdj[lo]);
        float fCur = __ldg(&rNrm[sCur]) * me;
        for (int i = lo; i < hi; i++) {
            int sNext = 0; float fNext = 0.f;
            if (i + 1 < hi) {
                sNext = __ldg(&rAdj[i + 1]);
                fNext = __ldg(&rNrm[sNext]) * me;
            }
            float4 v = __ldg(&h3[(size_t)sCur * 32 + L]);
            acc.x = fmaf(fCur, v.x, acc.x); acc.y = fmaf(fCur, v.y, acc.y);
            acc.z = fmaf(fCur, v.z, acc.z); acc.w = fmaf(fCur, v.w, acc.w);
            sCur = sNext; fCur = fNext;
        }
    }

    // relu(acc + b3) then bf16 dot with W[128,2]
    float4 bb = ((const float4*)b3)[L];
    float v[4] = {acc.x + bb.x, acc.y + bb.y, acc.z + bb.z, acc.w + bb.w};
    float c0 = 0.f, c1 = 0.f;
#pragma unroll
    for (int j = 0; j < 4; j++) {
        float w = rBf(fmaxf(v[j], 0.f));
        int k = L * 4 + j;
        c0 = fmaf(w, rBf(W[k * 2 + 0]), c0);
        c1 = fmaf(w, rBf(W[k * 2 + 1]), c1);
    }
#pragma unroll
    for (int o = 16; o; o >>= 1) {
        c0 += __shfl_xor_sync(~0u, c0, o);
        c1 += __shfl_xor_sync(~0u, c1, o);
    }
    if (L == 0) {
        rH4[n * 2 + 0] = c0;
        rH4[n * 2 + 1] = c1;
        rAs[n] = rBf(c0) * rBf(aS[0]) + rBf(c1) * rBf(aS[1]);
        rAd[n] = rBf(c0) * rBf(aD[0]) + rBf(c1) * rBf(aD[1]);
    }
}

__global__ void rkGat2() {
    int tid = blockIdx.x * blockDim.x + threadIdx.x;
    int n = tid >> 4;
    int L = tid & 15;
    if (n >= RN) return;
    int lo = rRow[n], hi = rRow[n + 1];
    float cd = rAd[n];
    const unsigned HM = 0xFFFFu << (threadIdx.x & 16);

    float mx = -INFINITY;
    for (int i = lo + L; i < hi; i += 16)
        mx = fmaxf(mx, rLk(__ldg(&rAs[__ldg(&rAdj[i])]) + cd));
#pragma unroll
    for (int o = 8; o; o >>= 1) mx = fmaxf(mx, __shfl_xor_sync(HM, mx, o));

    float dn = 0.f;
    for (int i = lo + L; i < hi; i += 16)
        dn += expf(rLk(__ldg(&rAs[__ldg(&rAdj[i])]) + cd) - mx);
#pragma unroll
    for (int o = 8; o; o >>= 1) dn += __shfl_xor_sync(HM, dn, o);
    float iv = 1.f / (dn + 1e-16f);

    float p = 0.f, q = 0.f;
    for (int i = lo + L; i < hi; i += 16) {
        int s = __ldg(&rAdj[i]);
        float w = expf(rLk(__ldg(&rAs[s]) + cd) - mx) * iv;
        p = fmaf(w, __ldg(&rH4[s * 2 + 0]), p);
        q = fmaf(w, __ldg(&rH4[s * 2 + 1]), q);
    }
#pragma unroll
    for (int o = 8; o; o >>= 1) {
        p += __shfl_xor_sync(HM, p, o);
        q += __shfl_xor_sync(HM, q, o);
    }
    if (L == 0) {
        rG4[n * 2 + 0] = p;
        rG4[n * 2 + 1] = q;
    }
}

__global__ void rkEmit(const float* __restrict__ b, float* __restrict__ out) {
    int n = blockIdx.x * blockDim.x + threadIdx.x;
    if (n >= RN) return;
    float v0 = rG4[n * 2 + 0] + b[0];
    float v1 = rG4[n * 2 + 1] + b[1];
    float m = fmaxf(v0, v1);
    float z = m + logf(expf(v0 - m) + expf(v1 - m));
    out[n * 2 + 0] = v0 - z;
    out[n * 2 + 1] = v1 - z;
}

}  // namespace r15

static inline int rcd(int a, int b) { return (a + b - 1) / b; }

extern "C" void kernel_launch(void* const* d_in, const int* in_sizes, int n_in,
                              void* d_out, int out_size) {
    using namespace r15;
    const float* x  = (const float*)d_in[0];
    const void*  ei = d_in[1];
    const float* W1 = (const float*)d_in[2];
    const float* b1 = (const float*)d_in[3];
    const float* W2 = (const float*)d_in[4];
    const float* s2 = (const float*)d_in[5];
    const float* d2 = (const float*)d_in[6];
    const float* b2 = (const float*)d_in[7];
    const float* W3 = (const float*)d_in[8];
    const float* b3 = (const float*)d_in[9];
    const float* W4 = (const float*)d_in[10];
    const float* s4 = (const float*)d_in[11];
    const float* d4 = (const float*)d_in[12];
    const float* b4 = (const float*)d_in[13];
    float* out = (float*)d_out;

    void *pd, *pc;
    cudaGetSymbolAddress(&pd, rDeg);
    cudaGetSymbolAddress(&pc, rCur);

    cudaMemsetAsync(pd, 0, sizeof(int) * RN);
    cudaMemsetAsync(pc, 0, sizeof(int) * RN);
    rkProbe<<<1, 32>>>(ei);
    rkDecode<<<rcd(RT, 256), 256>>>(ei);
    rkScanA<<<RSG, RSB>>>();
    rkScanB<<<1, 256>>>();
    rkScanC<<<rcd(RN, 256), 256>>>();
    rkPlace<<<rcd(RT, 256), 256>>>();

    // L1: GCN 7→32
    rkProj<7, 32, 8, false><<<rcd(RN, 8), dim3(32, 8)>>>(x, W1, nullptr, rH1);
    rkGcn32<<<rcd(RN * 16, 256), 256>>>(rH1, rG1);

    // L2: GAT 32→64 (GEMM + alpha fused)
    rkProj64A<<<rcd(RN, 4), dim3(64, 4)>>>(rG1, W2, b1, s2, d2, rH2);
    rkGat64<<<rcd(RN * 32, 256), 256>>>((const float2*)rH2, (float2*)rG2);

    // L3 projection: 64→128 (relu(agg2+b2) fused into input)
    rkProj<64, 128, 2, true><<<rcd(RN, 2), dim3(128, 2)>>>(rG2, W3, b2, rH3);

    // L3 gather + L4 head GEMM + alpha, fused (no 128-ch aggregate buffer)
    rkGatherHead<<<rcd(RN * 32, 256), 256>>>((const float4*)rH3, W4, b3, s4, d4);
    rkGat2<<<rcd(RN * 16, 256), 256>>>();

    rkEmit<<<rcd(RN, 256), 256>>>(b4, out);
}

// round 16
// speedup vs baseline: 1.1031x; 1.1031x over previous
// ============================================================================
// gNet_62285615727179 rev G16 — first PASSING lineage (R15: 8852us, 5.8e-5).
// GCN(7→32)+relu → GAT(32→64)+relu → GCN(64→128)+relu → GAT(128→2) → log_softmax
// Dense: RNE-bf16 operands / fp32 accumulate (confirmed matching reference).
// This rev: 11 launches (was 16), single-block scan, 2-way-unrolled gathers,
// gcn32 positioned at ncu capture slot #6.
// ============================================================================
#include <cuda_runtime.h>
#include <cuda_bf16.h>
#include <math.h>

namespace g16 {

constexpr int GN  = 100000;
constexpr int GE  = 1600000;
constexpr int GT  = GE + GN;

__device__ int   gDeg[GN];
__device__ int   gCur[GN];
__device__ float gNrm[GN];
__device__ int   gIs64;
__device__ int   gSrc[GT];
__device__ int   gDst[GT];
__device__ int   gRow[GN + 1];
__device__ int   gAdj[GT];

__device__ float gH1[GN * 32];
__device__ float gG1[GN * 32];
__device__ float gH2[GN * 64];
__device__ float gG2[GN * 64];
__device__ float gH3[(size_t)GN * 128];
__device__ float gH4[GN * 2];
__device__ float gAs[GN];
__device__ float gAd[GN];

__device__ __forceinline__ float gLk(float x) { return x > 0.f ? x : 0.2f * x; }
__device__ __forceinline__ float gBf(float x) {
    return __bfloat162float(__float2bfloat16(x));   // RNE bf16 operand rounding
}

// 1. init: zero deg/cur (grid-stride) + dtype probe (thread 0)
__global__ void gkInit(const void* raw) {
    int i = blockIdx.x * blockDim.x + threadIdx.x;
    if (i < GN) { gDeg[i] = 0; gCur[i] = 0; }
    if (i == 0) {
        const int* p = (const int*)raw;
        int m = 0;
        for (int k = 1; k < 128; k += 2) m |= p[k];
        gIs64 = (m == 0);
    }
}

// 2. dense projection (generic)
template <int CI, int CO, int RW, bool PRELU>
__global__ void gkProj(const float* __restrict__ in, const float* __restrict__ W,
                       const float* __restrict__ bias, float* __restrict__ out) {
    __shared__ float sw[CI * CO];
    __shared__ float sx[RW][CI];
    int flat = threadIdx.y * CO + threadIdx.x;
    for (int i = flat; i < CI * CO; i += CO * RW) sw[i] = gBf(W[i]);
    int n = blockIdx.x * RW + threadIdx.y;
    if (n < GN && threadIdx.x < CI) {
        float v = in[(size_t)n * CI + threadIdx.x];
        if (PRELU) v = fmaxf(v + bias[threadIdx.x], 0.f);
        sx[threadIdx.y][threadIdx.x] = gBf(v);
    }
    __syncthreads();
    if (n >= GN) return;
    float a = 0.f;
#pragma unroll
    for (int k = 0; k < CI; k++)
        a = fmaf(sx[threadIdx.y][k], sw[k * CO + threadIdx.x], a);
    out[(size_t)n * CO + threadIdx.x] = a;
}

// 3. decode edges + degree histogram
__global__ void gkDecode(const void* raw) {
    int e = blockIdx.x * blockDim.x + threadIdx.x;
    if (e >= GT) return;
    int s, d;
    if (e >= GE) {
        s = d = e - GE;
    } else if (gIs64) {
        const long long* p = (const long long*)raw;
        s = (int)p[e]; d = (int)p[GE + e];
    } else {
        const int* p = (const int*)raw;
        s = p[e]; d = p[GE + e];
    }
    gSrc[e] = s; gDst[e] = d;
    atomicAdd(&gDeg[d], 1);
}

// 4. single-block scan: rowptr = exscan(deg), nrm = rsqrt(deg)
__global__ void gkScan() {
    constexpr int TH = 1024;
    constexpr int CH = (GN + TH - 1) / TH;   // 98
    __shared__ int sh[TH];
    int t = threadIdx.x;
    int base = t * CH;
    int sum = 0;
    for (int j = 0; j < CH; j++) {
        int i = base + j;
        if (i < GN) sum += gDeg[i];
    }
    sh[t] = sum; __syncthreads();
    for (int o = 1; o < TH; o <<= 1) {
        int v = (t >= o) ? sh[t - o] : 0; __syncthreads();
        sh[t] += v; __syncthreads();
    }
    int run = sh[t] - sum;                   // exclusive prefix of chunk
    for (int j = 0; j < CH; j++) {
        int i = base + j;
        if (i < GN) {
            gRow[i] = run;
            int dg = gDeg[i];
            run += dg;
            gNrm[i] = dg > 0 ? rsqrtf((float)dg) : 0.f;
        }
    }
    if (t == 0) gRow[GN] = GT;
}

// 5. bucket edges into CSR
__global__ void gkPlace() {
    int e = blockIdx.x * blockDim.x + threadIdx.x;
    if (e >= GT) return;
    int d = gDst[e];
    gAdj[gRow[d] + atomicAdd(&gCur[d], 1)] = gSrc[e];
}

// 6. GCN 32-ch gather: half-warp/node, 2-way edge unroll
__global__ void gkGcn32(const float* __restrict__ h, float* __restrict__ y) {
    int tid = blockIdx.x * blockDim.x + threadIdx.x;
    int n = tid >> 4, L = tid & 15;
    if (n >= GN) return;
    int lo = gRow[n], hi = gRow[n + 1];
    float me = gNrm[n];
    float a0 = 0.f, a1 = 0.f, b0 = 0.f, b1 = 0.f;
    int i = lo;
    for (; i + 1 < hi; i += 2) {
        int s0 = __ldg(&gAdj[i]), s1 = __ldg(&gAdj[i + 1]);
        float f0 = __ldg(&gNrm[s0]) * me, f1 = __ldg(&gNrm[s1]) * me;
        a0 = fmaf(f0, __ldg(&h[(size_t)s0 * 32 + L]), a0);
        a1 = fmaf(f0, __ldg(&h[(size_t)s0 * 32 + 16 + L]), a1);
        b0 = fmaf(f1, __ldg(&h[(size_t)s1 * 32 + L]), b0);
        b1 = fmaf(f1, __ldg(&h[(size_t)s1 * 32 + 16 + L]), b1);
    }
    if (i < hi) {
        int s = __ldg(&gAdj[i]);
        float f = __ldg(&gNrm[s]) * me;
        a0 = fmaf(f, __ldg(&h[(size_t)s * 32 + L]), a0);
        a1 = fmaf(f, __ldg(&h[(size_t)s * 32 + 16 + L]), a1);
    }
    y[(size_t)n * 32 + L] = a0 + b0;
    y[(size_t)n * 32 + 16 + L] = a1 + b1;
}

// 7. 32→64 projection + fused alpha scores
__global__ void gkProj64A(const float* __restrict__ in, const float* __restrict__ W,
                          const float* __restrict__ bias,
                          const float* __restrict__ aS, const float* __restrict__ aD,
                          float* __restrict__ out) {
    constexpr int CI = 32, CO = 64, RW = 4;
    __shared__ float sw[CI * CO];
    __shared__ float sx[RW][CI];
    __shared__ float red[RW][2][2];
    int tx = threadIdx.x, ty = threadIdx.y;
    int flat = ty * CO + tx;
    for (int i = flat; i < CI * CO; i += CO * RW) sw[i] = gBf(W[i]);
    int n = blockIdx.x * RW + ty;
    if (n < GN && tx < CI) {
        float v = fmaxf(in[(size_t)n * CI + tx] + bias[tx], 0.f);
        sx[ty][tx] = gBf(v);
    }
    __syncthreads();

    float a = 0.f;
    if (n < GN) {
#pragma unroll
        for (int k = 0; k < CI; k++)
            a = fmaf(sx[ty][k], sw[k * CO + tx], a);
        out[(size_t)n * CO + tx] = a;
    }
    float pS = (n < GN) ? gBf(a) * gBf(aS[tx]) : 0.f;
    float pD = (n < GN) ? gBf(a) * gBf(aD[tx]) : 0.f;
#pragma unroll
    for (int o = 16; o; o >>= 1) {
        pS += __shfl_xor_sync(~0u, pS, o);
        pD += __shfl_xor_sync(~0u, pD, o);
    }
    if ((tx & 31) == 0) {
        red[ty][tx >> 5][0] = pS;
        red[ty][tx >> 5][1] = pD;
    }
    __syncthreads();
    if (tx == 0 && n < GN) {
        gAs[n] = red[ty][0][0] + red[ty][1][0];
        gAd[n] = red[ty][0][1] + red[ty][1][1];
    }
}

// 8. GAT 64-ch: warp/node, smem-staged weights, 2-way unrolled gather
__global__ void gkGat64(const float2* __restrict__ h, float2* __restrict__ y) {
    __shared__ float sWgt[8][32];
    int wid = threadIdx.x >> 5;
    int n = (blockIdx.x * blockDim.x + threadIdx.x) >> 5;
    int L = threadIdx.x & 31;
    if (n >= GN) return;
    int lo = gRow[n], hi = gRow[n + 1];
    float cd = gAd[n];

    float mx = -INFINITY;
    for (int i = lo + L; i < hi; i += 32)
        mx = fmaxf(mx, gLk(__ldg(&gAs[__ldg(&gAdj[i])]) + cd));
#pragma unroll
    for (int o = 16; o; o >>= 1) mx = fmaxf(mx, __shfl_xor_sync(~0u, mx, o));

    float dn = 0.f;
    for (int i = lo + L; i < hi; i += 32)
        dn += expf(gLk(__ldg(&gAs[__ldg(&gAdj[i])]) + cd) - mx);
#pragma unroll
    for (int o = 16; o; o >>= 1) dn += __shfl_xor_sync(~0u, dn, o);
    float iv = 1.f / (dn + 1e-16f);

    float2 a = make_float2(0.f, 0.f), b = make_float2(0.f, 0.f);
    for (int base = lo; base < hi; base += 32) {
        int i = base + L;
        sWgt[wid][L] = (i < hi)
            ? expf(gLk(__ldg(&gAs[__ldg(&gAdj[i])]) + cd) - mx) * iv : 0.f;
        __syncwarp();
        int cnt = min(32, hi - base);
        int j = 0;
        for (; j + 1 < cnt; j += 2) {
            int s0 = __ldg(&gAdj[base + j]), s1 = __ldg(&gAdj[base + j + 1]);
            float w0 = sWgt[wid][j], w1 = sWgt[wid][j + 1];
            float2 v0 = __ldg(&h[(size_t)s0 * 32 + L]);
            float2 v1 = __ldg(&h[(size_t)s1 * 32 + L]);
            a.x = fmaf(w0, v0.x, a.x); a.y = fmaf(w0, v0.y, a.y);
            b.x = fmaf(w1, v1.x, b.x); b.y = fmaf(w1, v1.y, b.y);
        }
        if (j < cnt) {
            int s = __ldg(&gAdj[base + j]);
            float w = sWgt[wid][j];
            float2 v = __ldg(&h[(size_t)s * 32 + L]);
            a.x = fmaf(w, v.x, a.x); a.y = fmaf(w, v.y, a.y);
        }
        __syncwarp();
    }
    y[(size_t)n * 32 + L] = make_float2(a.x + b.x, a.y + b.y);
}

// 10. FUSED: 128-ch GCN gather + relu(+b3) + 128→2 head + alpha (2-way unroll)
__global__ void gkGatherHead(const float4* __restrict__ h3,
                             const float* __restrict__ W,
                             const float* __restrict__ b3,
                             const float* __restrict__ aS,
                             const float* __restrict__ aD) {
    int n = (blockIdx.x * blockDim.x + threadIdx.x) >> 5;
    int L = threadIdx.x & 31;
    if (n >= GN) return;
    int lo = gRow[n], hi = gRow[n + 1];
    float me = gNrm[n];

    float4 a = make_float4(0.f, 0.f, 0.f, 0.f);
    float4 b = make_float4(0.f, 0.f, 0.f, 0.f);
    int i = lo;
    for (; i + 1 < hi; i += 2) {
        int s0 = __ldg(&gAdj[i]), s1 = __ldg(&gAdj[i + 1]);
        float f0 = __ldg(&gNrm[s0]) * me, f1 = __ldg(&gNrm[s1]) * me;
        float4 v0 = __ldg(&h3[(size_t)s0 * 32 + L]);
        float4 v1 = __ldg(&h3[(size_t)s1 * 32 + L]);
        a.x = fmaf(f0, v0.x, a.x); a.y = fmaf(f0, v0.y, a.y);
        a.z = fmaf(f0, v0.z, a.z); a.w = fmaf(f0, v0.w, a.w);
        b.x = fmaf(f1, v1.x, b.x); b.y = fmaf(f1, v1.y, b.y);
        b.z = fmaf(f1, v1.z, b.z); b.w = fmaf(f1, v1.w, b.w);
    }
    if (i < hi) {
        int s = __ldg(&gAdj[i]);
        float f = __ldg(&gNrm[s]) * me;
        float4 v = __ldg(&h3[(size_t)s * 32 + L]);
        a.x = fmaf(f, v.x, a.x); a.y = fmaf(f, v.y, a.y);
        a.z = fmaf(f, v.z, a.z); a.w = fmaf(f, v.w, a.w);
    }
    a.x += b.x; a.y += b.y; a.z += b.z; a.w += b.w;

    float4 bb = ((const float4*)b3)[L];
    float v[4] = {a.x + bb.x, a.y + bb.y, a.z + bb.z, a.w + bb.w};
    float c0 = 0.f, c1 = 0.f;
#pragma unroll
    for (int j = 0; j < 4; j++) {
        float w = gBf(fmaxf(v[j], 0.f));
        int k = L * 4 + j;
        c0 = fmaf(w, gBf(W[k * 2 + 0]), c0);
        c1 = fmaf(w, gBf(W[k * 2 + 1]), c1);
    }
#pragma unroll
    for (int o = 16; o; o >>= 1) {
        c0 += __shfl_xor_sync(~0u, c0, o);
        c1 += __shfl_xor_sync(~0u, c1, o);
    }
    if (L == 0) {
        gH4[n * 2 + 0] = c0;
        gH4[n * 2 + 1] = c1;
        gAs[n] = gBf(c0) * gBf(aS[0]) + gBf(c1) * gBf(aS[1]);
        gAd[n] = gBf(c0) * gBf(aD[0]) + gBf(c1) * gBf(aD[1]);
    }
}

// 11. GAT 2-ch + bias + log_softmax, fused, half-warp/node
__global__ void gkGat2Emit(const float* __restrict__ b4, float* __restrict__ out) {
    int tid = blockIdx.x * blockDim.x + threadIdx.x;
    int n = tid >> 4;
    int L = tid & 15;
    if (n >= GN) return;
    int lo = gRow[n], hi = gRow[n + 1];
    float cd = gAd[n];
    const unsigned HM = 0xFFFFu << (threadIdx.x & 16);

    float mx = -INFINITY;
    for (int i = lo + L; i < hi; i += 16)
        mx = fmaxf(mx, gLk(__ldg(&gAs[__ldg(&gAdj[i])]) + cd));
#pragma unroll
    for (int o = 8; o; o >>= 1) mx = fmaxf(mx, __shfl_xor_sync(HM, mx, o));

    float dn = 0.f;
    for (int i = lo + L; i < hi; i += 16)
        dn += expf(gLk(__ldg(&gAs[__ldg(&gAdj[i])]) + cd) - mx);
#pragma unroll
    for (int o = 8; o; o >>= 1) dn += __shfl_xor_sync(HM, dn, o);
    float iv = 1.f / (dn + 1e-16f);

    float p = 0.f, q = 0.f;
    for (int i = lo + L; i < hi; i += 16) {
        int s = __ldg(&gAdj[i]);
        float w = expf(gLk(__ldg(&gAs[s]) + cd) - mx) * iv;
        p = fmaf(w, __ldg(&gH4[s * 2 + 0]), p);
        q = fmaf(w, __ldg(&gH4[s * 2 + 1]), q);
    }
#pragma unroll
    for (int o = 8; o; o >>= 1) {
        p += __shfl_xor_sync(HM, p, o);
        q += __shfl_xor_sync(HM, q, o);
    }
    if (L == 0) {
        float v0 = p + b4[0];
        float v1 = q + b4[1];
        float m = fmaxf(v0, v1);
        float z = m + logf(expf(v0 - m) + expf(v1 - m));
        out[n * 2 + 0] = v0 - z;
        out[n * 2 + 1] = v1 - z;
    }
}

}  // namespace g16

static inline int gcd_(int a, int b) { return (a + b - 1) / b; }

extern "C" void kernel_launch(void* const* d_in, const int* in_sizes, int n_in,
                              void* d_out, int out_size) {
    using namespace g16;
    const float* x  = (const float*)d_in[0];
    const void*  ei = d_in[1];
    const float* W1 = (const float*)d_in[2];
    const float* b1 = (const float*)d_in[3];
    const float* W2 = (const float*)d_in[4];
    const float* s2 = (const float*)d_in[5];
    const float* d2 = (const float*)d_in[6];
    const float* b2 = (const float*)d_in[7];
    const float* W3 = (const float*)d_in[8];
    const float* b3 = (const float*)d_in[9];
    const float* W4 = (const float*)d_in[10];
    const float* s4 = (const float*)d_in[11];
    const float* d4 = (const float*)d_in[12];
    const float* b4 = (const float*)d_in[13];
    float* out = (float*)d_out;

    // slot 1: init (zero deg/cur + dtype probe)
    gkInit<<<gcd_(GN, 512), 512>>>(ei);
    // slot 2: L1 projection (independent of graph)
    gkProj<7, 32, 8, false><<<gcd_(GN, 8), dim3(32, 8)>>>(x, W1, nullptr, gH1);
    // slot 3-5: graph assembly
    gkDecode<<<gcd_(GT, 256), 256>>>(ei);
    gkScan<<<1, 1024>>>();
    gkPlace<<<gcd_(GT, 256), 256>>>();
    // slot 6: first hot gather (ncu capture lands here)
    gkGcn32<<<gcd_(GN * 16, 256), 256>>>(gH1, gG1);
    // slot 7-8: GAT 32→64
    gkProj64A<<<gcd_(GN, 4), dim3(64, 4)>>>(gG1, W2, b1, s2, d2, gH2);
    gkGat64<<<gcd_(GN * 32, 256), 256>>>((const float2*)gH2, (float2*)gG2);
    // slot 9: 64→128 projection
    gkProj<64, 128, 2, true><<<gcd_(GN, 2), dim3(128, 2)>>>(gG2, W3, b2, gH3);
    // slot 10: fused 128-ch gather + head GEMM + alpha
    gkGatherHead<<<gcd_(GN * 32, 256), 256>>>((const float4*)gH3, W4, b3, s4, d4);
    // slot 11: GAT 2-ch + log_softmax → out
    gkGat2Emit<<<gcd_(GN * 16, 256), 256>>>(b4, out);
}